// round 8
// baseline (speedup 1.0000x reference)
#include <cuda_runtime.h>
#include <cuda_bf16.h>

// Shapes (fixed by setup_inputs): B=32, T=512, C=T-1=511, K=8, S=8, d=300
#define BB 32
#define CC 511
#define KK 8
#define SS 8
#define DD 300
#define D4 75      // DD/4 float4 per row
#define D2 150     // DD/2 float2 per row
#define TILE_C 32
#define NSPLIT 16  // ceil(511/32)
#define RSQRT300 0.057735026918962576f

// Scratch (device globals; no allocation allowed)
__device__ float g_pden[BB * NSPLIT * KK];        // partial sum of exp(a)
__device__ float g_mpart[BB * NSPLIT * KK * DD];  // partial unnormalized m'
__device__ float g_s[BB * KK];                    // cosine similarity

__device__ __forceinline__ float4 ldcs4(const float4* p) {
    return __ldcs(p);
}

// ---------------------------------------------------------------------------
// Main fused kernel. grid (NSPLIT=16, B=32) = 512 blocks, block 256 (8 warps).
// Phase A (warp per c): v = mean_s(ctx[c]) -> smem; dots for all 8 k fused
//   with the streaming (keeps DRAM busy); 8-dot reduction via 9-shuffle
//   value-halving butterfly; ew[k][c] = exp(a) (unnormalized, |a| small).
// Phase B (thread per float2 of d): m'[k][:] = sum_c ew[k][c] * v[c][:]
// Natural register allocation (NO forced launch bounds -- R6 spill lesson).
// ---------------------------------------------------------------------------
__global__ __launch_bounds__(256) void k_main(const float* __restrict__ ctx,
                                              const float* __restrict__ center) {
    const int b = blockIdx.y;
    const int tile = blockIdx.x;
    __shared__ float4 cen[KK * D4];        // 9600 B
    __shared__ float4 vt[TILE_C * D4];     // 38400 B
    __shared__ float ew[KK][TILE_C];       // 1024 B  (total 49024 <= 48KB+)

    {
        const float4* cg = reinterpret_cast<const float4*>(center + (size_t)b * KK * DD);
        for (int i = threadIdx.x; i < KK * D4; i += blockDim.x) cen[i] = cg[i];
    }
    __syncthreads();

    const int w = threadIdx.x >> 5;
    const int lane = threadIdx.x & 31;
    const int j0 = lane, j1 = lane + 32, j2 = lane + 64;
    const bool p2 = (j2 < D4);

    const int c0 = tile * TILE_C;
    int cn = CC - c0; if (cn > TILE_C) cn = TILE_C;

    // ---- Phase A: warp w handles ci = w, w+8, w+16, w+24 ----
    for (int ci = w; ci < cn; ci += 8) {
        const int c = c0 + ci;
        const float4* p = reinterpret_cast<const float4*>(ctx) + (size_t)(b * CC + c) * (SS * D4);
        float4 a0 = {0.f, 0.f, 0.f, 0.f}, a1 = a0, a2 = a0;
#pragma unroll
        for (int s = 0; s < SS; s++) {
            const float4* ps = p + s * D4;
            float4 x0 = ldcs4(ps + j0);
            float4 x1 = ldcs4(ps + j1);
            a0.x += x0.x; a0.y += x0.y; a0.z += x0.z; a0.w += x0.w;
            a1.x += x1.x; a1.y += x1.y; a1.z += x1.z; a1.w += x1.w;
            if (p2) {
                float4 x2 = ldcs4(ps + j2);
                a2.x += x2.x; a2.y += x2.y; a2.z += x2.z; a2.w += x2.w;
            }
        }
        const float sc = 1.0f / (float)SS;
        a0.x *= sc; a0.y *= sc; a0.z *= sc; a0.w *= sc;
        a1.x *= sc; a1.y *= sc; a1.z *= sc; a1.w *= sc;
        a2.x *= sc; a2.y *= sc; a2.z *= sc; a2.w *= sc;

        vt[ci * D4 + j0] = a0;
        vt[ci * D4 + j1] = a1;
        if (p2) vt[ci * D4 + j2] = a2;

        // per-lane partial dots for all 8 k
        float t[KK];
#pragma unroll
        for (int k = 0; k < KK; k++) {
            float4 c0v = cen[k * D4 + j0];
            float4 c1v = cen[k * D4 + j1];
            float s = a0.x * c0v.x + a0.y * c0v.y + a0.z * c0v.z + a0.w * c0v.w
                    + a1.x * c1v.x + a1.y * c1v.y + a1.z * c1v.z + a1.w * c1v.w;
            if (p2) {
                float4 c2v = cen[k * D4 + j2];
                s += a2.x * c2v.x + a2.y * c2v.y + a2.z * c2v.z + a2.w * c2v.w;
            }
            t[k] = s;
        }

        // value-halving butterfly: 8 sums in 9 shuffles.
        // After steps, lane l (l<8) holds sum for k = ((l&1)<<2)|(l&2)|((l>>2)&1)
        float t4[4];
        {
            const bool sel = lane & 1;
#pragma unroll
            for (int j = 0; j < 4; j++) {
                float keep = sel ? t[j + 4] : t[j];
                float give = sel ? t[j] : t[j + 4];
                t4[j] = keep + __shfl_xor_sync(0xffffffffu, give, 1);
            }
        }
        float t2[2];
        {
            const bool sel = lane & 2;
#pragma unroll
            for (int j = 0; j < 2; j++) {
                float keep = sel ? t4[j + 2] : t4[j];
                float give = sel ? t4[j] : t4[j + 2];
                t2[j] = keep + __shfl_xor_sync(0xffffffffu, give, 2);
            }
        }
        float t1;
        {
            const bool sel = lane & 4;
            float keep = sel ? t2[1] : t2[0];
            float give = sel ? t2[0] : t2[1];
            t1 = keep + __shfl_xor_sync(0xffffffffu, give, 4);
        }
        t1 += __shfl_xor_sync(0xffffffffu, t1, 8);
        t1 += __shfl_xor_sync(0xffffffffu, t1, 16);

        if (lane < KK) {
            const int kk = ((lane & 1) << 2) | (lane & 2) | ((lane >> 2) & 1);
            ew[kk][ci] = __expf(t1 * RSQRT300);
        }
    }
    __syncthreads();

    // ---- pden partials ----
    if (threadIdx.x < KK) {
        const int k = threadIdx.x;
        float s = 0.f;
        for (int cc = 0; cc < cn; cc++) s += ew[k][cc];
        g_pden[(b * NSPLIT + tile) * KK + k] = s;
    }

    // ---- Phase B ----
    const int t = threadIdx.x;
    if (t < D2) {
        float2 acc[KK];
#pragma unroll
        for (int k = 0; k < KK; k++) acc[k] = make_float2(0.f, 0.f);

        const float2* vf = reinterpret_cast<const float2*>(vt);
#pragma unroll 4
        for (int cc = 0; cc < cn; cc++) {
            float2 v2 = vf[cc * D2 + t];
#pragma unroll
            for (int k = 0; k < KK; k++) {
                float al = ew[k][cc];
                acc[k].x += al * v2.x;
                acc[k].y += al * v2.y;
            }
        }
        float2* mp = reinterpret_cast<float2*>(g_mpart) + (size_t)((b * NSPLIT + tile) * KK) * D2;
#pragma unroll
        for (int k = 0; k < KK; k++) mp[k * D2 + t] = acc[k];
    }
}

// ---------------------------------------------------------------------------
// Cosine similarity per (b,k). grid (KK, BB) = 256 blocks, block 160 (5 warps)
// ---------------------------------------------------------------------------
__global__ __launch_bounds__(160) void k_sim(const float* __restrict__ center) {
    const int k = blockIdx.x;
    const int b = blockIdx.y;
    const int t = threadIdx.x;
    const int w = t >> 5, lane = t & 31;
    __shared__ float red[3][5];

    float num = 0.f, n1 = 0.f, n2 = 0.f;
    if (t < D2) {
        const float2* cp = reinterpret_cast<const float2*>(center + (size_t)(b * KK + k) * DD);
        float2 cv = cp[t];
        float2 mm = make_float2(0.f, 0.f);
#pragma unroll
        for (int s = 0; s < NSPLIT; s++) {
            const float2* mp = reinterpret_cast<const float2*>(g_mpart)
                             + (size_t)((b * NSPLIT + s) * KK + k) * D2;
            float2 x = mp[t];
            mm.x += x.x; mm.y += x.y;
        }
        num = cv.x * mm.x + cv.y * mm.y;
        n1  = cv.x * cv.x + cv.y * cv.y;
        n2  = mm.x * mm.x + mm.y * mm.y;
    }
#pragma unroll
    for (int off = 16; off > 0; off >>= 1) {
        num += __shfl_xor_sync(0xffffffffu, num, off);
        n1  += __shfl_xor_sync(0xffffffffu, n1, off);
        n2  += __shfl_xor_sync(0xffffffffu, n2, off);
    }
    if (lane == 0) { red[0][w] = num; red[1][w] = n1; red[2][w] = n2; }
    __syncthreads();
    if (t == 0) {
        float N = 0.f, A = 0.f, B2 = 0.f;
#pragma unroll
        for (int i = 0; i < 5; i++) { N += red[0][i]; A += red[1][i]; B2 += red[2][i]; }
        float dsum = 0.f;
#pragma unroll
        for (int s = 0; s < NSPLIT; s++) dsum += g_pden[(b * NSPLIT + s) * KK + k];
        float invd = 1.0f / dsum;
        float d1 = fmaxf(sqrtf(A), 1e-8f);
        float d2 = fmaxf(sqrtf(B2) * invd, 1e-8f);
        g_s[b * KK + k] = (N * invd) / (d1 * d2);
    }
}

// ---------------------------------------------------------------------------
// Epilogue: softmax over s -> q, argmax, pooled gather. grid 32, block 128.
// ---------------------------------------------------------------------------
__global__ __launch_bounds__(128) void k_out(const float* __restrict__ center,
                                             float* __restrict__ out) {
    const int b = blockIdx.x;
    __shared__ float sq[KK];
    __shared__ int sidx;

    if (threadIdx.x == 0) {
        float sv[KK];
#pragma unroll
        for (int i = 0; i < KK; i++) sv[i] = g_s[b * KK + i];
        float mx = sv[0]; int id = 0;
#pragma unroll
        for (int i = 1; i < KK; i++)
            if (sv[i] > mx) { mx = sv[i]; id = i; }
        float den = 0.f;
#pragma unroll
        for (int i = 0; i < KK; i++) den += __expf(sv[i] - mx);
        float invden = 1.0f / den;
#pragma unroll
        for (int i = 0; i < KK; i++) sq[i] = __expf(sv[i] - mx) * invden;
        sidx = id;
    }
    __syncthreads();

    if (threadIdx.x < KK)
        out[BB * DD + b * KK + threadIdx.x] = sq[threadIdx.x];

    if (threadIdx.x < D4) {
        const float4* src = reinterpret_cast<const float4*>(center + (size_t)(b * KK + sidx) * DD);
        float4* dst = reinterpret_cast<float4*>(out + (size_t)b * DD);
        dst[threadIdx.x] = src[threadIdx.x];
    }
}

// ---------------------------------------------------------------------------
extern "C" void kernel_launch(void* const* d_in, const int* in_sizes, int n_in,
                              void* d_out, int out_size) {
    // inputs: 0 center_pos(i32), 1 query_token_ids(i32) -- both mathematically dead
    //         2 center_sense_embeddings f32 [32,8,300]
    //         3 context_sense_embeddings f32 [32,511,8,300]
    const float* center = (const float*)d_in[2];
    const float* ctx    = (const float*)d_in[3];
    float* out = (float*)d_out;

    k_main<<<dim3(NSPLIT, BB), 256>>>(ctx, center);
    k_sim<<<dim3(KK, BB), 160>>>(center);
    k_out<<<BB, 128>>>(center, out);
}

// round 9
// speedup vs baseline: 1.1926x; 1.1926x over previous
#include <cuda_runtime.h>
#include <cuda_bf16.h>

// Shapes (fixed by setup_inputs): B=32, T=512, C=T-1=511, K=8, S=8, d=300
#define BB 32
#define CC 511
#define KK 8
#define SS 8
#define DD 300
#define D4 75      // DD/4 float4 per row
#define D2 150     // DD/2 float2 per row
#define TILE_C 32
#define NSPLIT 16  // ceil(511/32)
#define RSQRT300 0.057735026918962576f

// Scratch (device globals; no allocation allowed)
__device__ float g_pden[BB * NSPLIT * KK];        // partial sum of exp(a)
__device__ float g_mpart[BB * NSPLIT * KK * DD];  // partial unnormalized m'
__device__ float g_s[BB * KK];                    // cosine similarity
__device__ int   g_cnt[BB];                       // completion counters per b

// ---------------------------------------------------------------------------
// Main fused kernel — EXACT R5 structure (proven 36.5us, do not perturb).
// grid (NSPLIT=16, B=32) = 512 blocks, block 256 (8 warps).
// Phase A (warp per c): v = mean_s(ctx[c]) -> smem; serial per-k 5-shuffle
//   dot reduce (immediate consume, no live arrays -> no spills);
//   ew[k][c] = exp(a) unnormalized (|a| small, safe).
// Phase B (thread per float2 of d): m'[k][:] = sum_c ew[k][c] * v[c][:]
// Also zeroes g_cnt for the fused epilogue (stream-ordered before k_sim).
// ---------------------------------------------------------------------------
__global__ __launch_bounds__(256) void k_main(const float* __restrict__ ctx,
                                              const float* __restrict__ center) {
    const int b = blockIdx.y;
    const int tile = blockIdx.x;
    __shared__ float4 cen[KK * D4];        // 9600 B
    __shared__ float4 vt[TILE_C * D4];     // 38400 B
    __shared__ float ew[KK][TILE_C];       // 1024 B

    if (tile == 0 && threadIdx.x == 0) g_cnt[b] = 0;

    {
        const float4* cg = reinterpret_cast<const float4*>(center + (size_t)b * KK * DD);
        for (int i = threadIdx.x; i < KK * D4; i += blockDim.x) cen[i] = cg[i];
    }
    __syncthreads();

    const int w = threadIdx.x >> 5;
    const int lane = threadIdx.x & 31;
    const int j0 = lane, j1 = lane + 32, j2 = lane + 64;
    const bool p2 = (j2 < D4);

    const int c0 = tile * TILE_C;
    int cn = CC - c0; if (cn > TILE_C) cn = TILE_C;

    // ---- Phase A ----
    for (int ci = w; ci < cn; ci += 8) {
        const int c = c0 + ci;
        const float4* p = reinterpret_cast<const float4*>(ctx) + (size_t)(b * CC + c) * (SS * D4);
        float4 a0 = {0.f, 0.f, 0.f, 0.f}, a1 = a0, a2 = a0;
#pragma unroll
        for (int s = 0; s < SS; s++) {
            const float4* ps = p + s * D4;
            float4 x0 = ps[j0];
            float4 x1 = ps[j1];
            a0.x += x0.x; a0.y += x0.y; a0.z += x0.z; a0.w += x0.w;
            a1.x += x1.x; a1.y += x1.y; a1.z += x1.z; a1.w += x1.w;
            if (p2) {
                float4 x2 = ps[j2];
                a2.x += x2.x; a2.y += x2.y; a2.z += x2.z; a2.w += x2.w;
            }
        }
        const float sc = 1.0f / (float)SS;
        a0.x *= sc; a0.y *= sc; a0.z *= sc; a0.w *= sc;
        a1.x *= sc; a1.y *= sc; a1.z *= sc; a1.w *= sc;
        a2.x *= sc; a2.y *= sc; a2.z *= sc; a2.w *= sc;

        vt[ci * D4 + j0] = a0;
        vt[ci * D4 + j1] = a1;
        if (p2) vt[ci * D4 + j2] = a2;

#pragma unroll
        for (int k = 0; k < KK; k++) {
            float4 c0v = cen[k * D4 + j0];
            float4 c1v = cen[k * D4 + j1];
            float t = a0.x * c0v.x + a0.y * c0v.y + a0.z * c0v.z + a0.w * c0v.w
                    + a1.x * c1v.x + a1.y * c1v.y + a1.z * c1v.z + a1.w * c1v.w;
            if (p2) {
                float4 c2v = cen[k * D4 + j2];
                t += a2.x * c2v.x + a2.y * c2v.y + a2.z * c2v.z + a2.w * c2v.w;
            }
#pragma unroll
            for (int off = 16; off > 0; off >>= 1)
                t += __shfl_xor_sync(0xffffffffu, t, off);
            if (lane == 0)
                ew[k][ci] = __expf(t * RSQRT300);
        }
    }
    __syncthreads();

    // ---- pden partials ----
    if (threadIdx.x < KK) {
        const int k = threadIdx.x;
        float s = 0.f;
        for (int cc = 0; cc < cn; cc++) s += ew[k][cc];
        g_pden[(b * NSPLIT + tile) * KK + k] = s;
    }

    // ---- Phase B ----
    const int t = threadIdx.x;
    if (t < D2) {
        float2 acc[KK];
#pragma unroll
        for (int k = 0; k < KK; k++) acc[k] = make_float2(0.f, 0.f);

        const float2* vf = reinterpret_cast<const float2*>(vt);
#pragma unroll 4
        for (int cc = 0; cc < cn; cc++) {
            float2 v2 = vf[cc * D2 + t];
#pragma unroll
            for (int k = 0; k < KK; k++) {
                float al = ew[k][cc];
                acc[k].x += al * v2.x;
                acc[k].y += al * v2.y;
            }
        }
        float2* mp = reinterpret_cast<float2*>(g_mpart) + (size_t)((b * NSPLIT + tile) * KK) * D2;
#pragma unroll
        for (int k = 0; k < KK; k++) mp[k * D2 + t] = acc[k];
    }
}

// ---------------------------------------------------------------------------
// Fused cosine-similarity + epilogue. grid (KK, BB) = 256 blocks, block 160.
// Each block computes s[b,k]; the LAST block to finish a given b (per-b
// atomic counter) performs softmax q, argmax, q-write and pooled copy.
// ---------------------------------------------------------------------------
__global__ __launch_bounds__(160) void k_sim(const float* __restrict__ center,
                                             float* __restrict__ out) {
    const int k = blockIdx.x;
    const int b = blockIdx.y;
    const int t = threadIdx.x;
    const int w = t >> 5, lane = t & 31;
    __shared__ float red[3][5];
    __shared__ float sq[KK];
    __shared__ int sflag;   // 1 => this block does the epilogue for b
    __shared__ int sidx;

    float num = 0.f, n1 = 0.f, n2 = 0.f;
    if (t < D2) {
        const float2* cp = reinterpret_cast<const float2*>(center + (size_t)(b * KK + k) * DD);
        float2 cv = cp[t];
        float2 mm = make_float2(0.f, 0.f);
#pragma unroll
        for (int s = 0; s < NSPLIT; s++) {
            const float2* mp = reinterpret_cast<const float2*>(g_mpart)
                             + (size_t)((b * NSPLIT + s) * KK + k) * D2;
            float2 x = mp[t];
            mm.x += x.x; mm.y += x.y;
        }
        num = cv.x * mm.x + cv.y * mm.y;
        n1  = cv.x * cv.x + cv.y * cv.y;
        n2  = mm.x * mm.x + mm.y * mm.y;
    }
#pragma unroll
    for (int off = 16; off > 0; off >>= 1) {
        num += __shfl_xor_sync(0xffffffffu, num, off);
        n1  += __shfl_xor_sync(0xffffffffu, n1, off);
        n2  += __shfl_xor_sync(0xffffffffu, n2, off);
    }
    if (lane == 0) { red[0][w] = num; red[1][w] = n1; red[2][w] = n2; }
    __syncthreads();

    if (t == 0) {
        float N = 0.f, A = 0.f, B2 = 0.f;
#pragma unroll
        for (int i = 0; i < 5; i++) { N += red[0][i]; A += red[1][i]; B2 += red[2][i]; }
        float dsum = 0.f;
#pragma unroll
        for (int s = 0; s < NSPLIT; s++) dsum += g_pden[(b * NSPLIT + s) * KK + k];
        float invd = 1.0f / dsum;
        float d1 = fmaxf(sqrtf(A), 1e-8f);
        float d2 = fmaxf(sqrtf(B2) * invd, 1e-8f);
        g_s[b * KK + k] = (N * invd) / (d1 * d2);

        __threadfence();                       // publish g_s before counting
        int old = atomicAdd(&g_cnt[b], 1);
        if (old == KK - 1) {
            __threadfence();                   // acquire: see others' g_s
            float sv[KK];
#pragma unroll
            for (int i = 0; i < KK; i++) sv[i] = __ldcg(&g_s[b * KK + i]);
            float mx = sv[0]; int id = 0;
#pragma unroll
            for (int i = 1; i < KK; i++)
                if (sv[i] > mx) { mx = sv[i]; id = i; }
            float den = 0.f;
#pragma unroll
            for (int i = 0; i < KK; i++) den += __expf(sv[i] - mx);
            float invden = 1.0f / den;
#pragma unroll
            for (int i = 0; i < KK; i++) sq[i] = __expf(sv[i] - mx) * invden;
            sidx = id;
            sflag = 1;
        } else {
            sflag = 0;
        }
    }
    __syncthreads();

    if (sflag) {
        if (t < KK)
            out[BB * DD + b * KK + t] = sq[t];
        if (t < D4) {
            const float4* src = reinterpret_cast<const float4*>(center + (size_t)(b * KK + sidx) * DD);
            float4* dst = reinterpret_cast<float4*>(out + (size_t)b * DD);
            dst[t] = src[t];
        }
    }
}

// ---------------------------------------------------------------------------
extern "C" void kernel_launch(void* const* d_in, const int* in_sizes, int n_in,
                              void* d_out, int out_size) {
    // inputs: 0 center_pos(i32), 1 query_token_ids(i32) -- both mathematically dead
    //         2 center_sense_embeddings f32 [32,8,300]
    //         3 context_sense_embeddings f32 [32,511,8,300]
    const float* center = (const float*)d_in[2];
    const float* ctx    = (const float*)d_in[3];
    float* out = (float*)d_out;

    k_main<<<dim3(NSPLIT, BB), 256>>>(ctx, center);
    k_sim<<<dim3(KK, BB), 160>>>(center, out);
}